// round 7
// baseline (speedup 1.0000x reference)
#include <cuda_runtime.h>
#include <math.h>

#define DD 512
#define PP 36
#define PS 37                        // padded row stride: conflict-free everywhere
#define NT 1024
#define EPSN 1e-12f
#define SCALE_CLS 7.0f
#define TILE_F (DD*PP)               // 18432 floats per gmem tile
#define JOBS   (TILE_F/4)            // 4608 float4 jobs per tensor

// SMEM layout (floats)
#define ST_OFF   0                   // test tile  [512][37]
#define SR_OFF   (DD*PS)             // train tile [512][37]
#define MEANS    (2*DD*PS)           // means [2][512]
#define FUSE     (MEANS + 2*DD)      // fused vectors [2][512]
#define NN       (FUSE + 2*DD)       // per-position norms [2][36] (pad 80)
#define SC       (NN + 80)           // selection scores [2][36]
#define WW       (SC + 80)           // fuse weights [2][36]
#define RED      (WW + 80)           // reduction scratch [48]
#define SMEMF    (RED + 48)
#define SMEMB    (SMEMF * 4)         // ~160.8 KB -> 1 CTA/SM, 1024 thr

__device__ __forceinline__ float warp_sum(float v) {
#pragma unroll
    for (int o = 16; o > 0; o >>= 1) v += __shfl_down_sync(0xffffffffu, v, o);
    return v;
}

__global__ __launch_bounds__(NT, 1)
void fused_region_score_w32(const float* __restrict__ ftrain,
                            const float* __restrict__ ftest,
                            const int*   __restrict__ Kp,
                            float* __restrict__ out,
                            int groups, int halfOut)
{
    extern __shared__ float sm[];
    float* st    = sm + ST_OFF;
    float* sr    = sm + SR_OFF;
    float* means = sm + MEANS;
    float* fuse  = sm + FUSE;
    float* red   = sm + RED;

    const int tid  = threadIdx.x;
    const int lane = tid & 31;
    const int wid  = tid >> 5;          // 0..31
    const int half = tid >> 9;          // 0 = test, 1 = train
    const int d    = tid & 511;
    const int K    = Kp[0];

    // contiguous group range per CTA
    const int nc = gridDim.x;
    const int q  = groups / nc, r = groups % nc;
    const int gbeg = blockIdx.x * q + min(blockIdx.x, r);
    const int gend = gbeg + q + (blockIdx.x < r ? 1 : 0);

    float* mytile = half ? sr : st;

    for (int g = gbeg; g < gend; g++) {
        // ---------------- load both tiles, coalesced, transpose via SMEM ----
        const float4* gt = (const float4*)(ftest  + (size_t)g * TILE_F);
        const float4* gr = (const float4*)(ftrain + (size_t)g * TILE_F);
#pragma unroll
        for (int k = 0; k < 4; k++) {
            int j = tid + k * NT;            // 0..4095, coalesced
            float4 a = gt[j];
            float4 b = gr[j];
            int dd = j / 9;
            int p  = (j - dd * 9) * 4;
            int s  = dd * PS + p;
            st[s] = a.x; st[s+1] = a.y; st[s+2] = a.z; st[s+3] = a.w;
            sr[s] = b.x; sr[s+1] = b.y; sr[s+2] = b.z; sr[s+3] = b.w;
        }
        if (tid < JOBS - 4 * NT) {           // remaining 512 jobs
            int j = tid + 4 * NT;
            float4 a = gt[j];
            float4 b = gr[j];
            int dd = j / 9;
            int p  = (j - dd * 9) * 4;
            int s  = dd * PS + p;
            st[s] = a.x; st[s+1] = a.y; st[s+2] = a.z; st[s+3] = a.w;
            sr[s] = b.x; sr[s+1] = b.y; sr[s+2] = b.z; sr[s+3] = b.w;
        }
        __syncthreads();                     // s1: tiles ready

        // ---------------- mean pass: thread (half,d) sums its row -----------
        {
            const float* row = mytile + d * PS;
            float s = 0.f;
#pragma unroll
            for (int p = 0; p < PP; p++) s += row[p];
            means[half * DD + d] = s * (1.0f / PP);
        }
        __syncthreads();                     // s2: means ready

        // ---------------- stage A partials (half 0) + stage B (all warps) ---
        if (half == 0) {
            float mt = means[d], mr = means[DD + d];
            float a = warp_sum(mt * mr);
            float b = warp_sum(mt * mt);
            float c = warp_sum(mr * mr);
            if (lane == 0) { red[wid] = a; red[16 + wid] = b; red[32 + wid] = c; }
        }

        // stage B: 72 jobs (tensor,p) over 32 warps
#pragma unroll
        for (int rr = 0; rr < 3; rr++) {
            if (rr == 2 && wid >= 8) break;
            const int j    = wid + 32 * rr;           // 0..71
            const int tens = (j >= PP) ? 1 : 0;
            const int p    = j - PP * tens;
            const float* X = tens ? sr : st;
            const float* M = means + (1 - tens) * DD; // other tensor's mean
            float a2 = 0.f, ta = 0.f;
#pragma unroll
            for (int i = 0; i < DD / 32; i++) {
                int dd = lane + 32 * i;
                float a = X[dd * PS + p];
                a2 += a * a;
                ta += a * M[dd];
            }
            a2 = warp_sum(a2);
            ta = warp_sum(ta);
            if (lane == 0) {
                float n = fmaxf(sqrtf(a2), EPSN);
                sm[NN + j] = n;
                sm[SC + j] = ta / n;   // positive constant factors cancel in ranking
            }
        }
        __syncthreads();                     // s3: SC/NN + stage-A red ready

        // ---------------- stage A final + stage C ----------------------------
        if (wid == 0) {
            float a = (lane < 16) ? red[lane]      : 0.f;
            float b = (lane < 16) ? red[16 + lane] : 0.f;
            float c = (lane < 16) ? red[32 + lane] : 0.f;
            a = warp_sum(a); b = warp_sum(b); c = warp_sum(c);
            if (lane == 0) {
                float den = fmaxf(sqrtf(b), EPSN) * fmaxf(sqrtf(c), EPSN);
                out[g] = SCALE_CLS * a / den;
            }
        }

        if (tid < 2 * PP) {                  // top-K via rank counting
            const int tens = (tid >= PP) ? 1 : 0;
            const int p    = tid - PP * tens;
            const int b0   = PP * tens;
            const float sv = sm[SC + tid];
            int rank = 0;
#pragma unroll
            for (int qq = 0; qq < PP; qq++) {
                float o = sm[SC + b0 + qq];
                rank += (o > sv) || (o == sv && qq < p);  // lower index wins ties
            }
            sm[WW + tid] = (rank < K) ? (1.0f / sm[NN + tid]) : 0.0f;
        }
        __syncthreads();                     // s4: weights ready

        // ---------------- stage D: fused vector per (half,d) -----------------
        float u = 0.f;
        {
            const float* row = mytile + d * PS;
            const float* w   = sm + WW + half * PP;
#pragma unroll
            for (int p = 0; p < PP; p++) u += row[p] * w[p];
        }
        if (half == 1) fuse[DD + d] = u;     // train fused vector published
        __syncthreads();                     // s5: fuse ready

        // ---------------- final score reductions (half 0) --------------------
        if (half == 0) {
            float v = fuse[DD + d];
            float a = warp_sum(u * v);
            float b = warp_sum(u * u);
            float c = warp_sum(v * v);
            if (lane == 0) { red[wid] = a; red[16 + wid] = b; red[32 + wid] = c; }
        }
        __syncthreads();                     // s6: red ready (tile reads done)

        if (wid == 0) {
            float a = (lane < 16) ? red[lane]      : 0.f;
            float b = (lane < 16) ? red[16 + lane] : 0.f;
            float c = (lane < 16) ? red[32 + lane] : 0.f;
            a = warp_sum(a); b = warp_sum(b); c = warp_sum(c);
            if (lane == 0) {
                float den = fmaxf(sqrtf(b), EPSN) * fmaxf(sqrtf(c), EPSN);
                out[halfOut + g] = SCALE_CLS * a / den;
            }
        }
        // wid0's red reads precede its arrival at next iteration's s1/s2;
        // other warps rewrite red only after next s2 -> ordered, no extra sync.
    }
}

extern "C" void kernel_launch(void* const* d_in, const int* in_sizes, int n_in,
                              void* d_out, int out_size)
{
    const float* ftrain = (const float*)d_in[0];
    const float* ftest  = (const float*)d_in[1];
    const int*   Kp     = (const int*)d_in[2];
    float* out = (float*)d_out;

    const int groups  = in_sizes[0] / (DD * PP);   // 1500
    const int halfOut = out_size / 2;              // 1500

    cudaFuncSetAttribute(fused_region_score_w32,
                         cudaFuncAttributeMaxDynamicSharedMemorySize, SMEMB);
    fused_region_score_w32<<<148, NT, SMEMB>>>(ftrain, ftest, Kp, out,
                                               groups, halfOut);
}